// round 15
// baseline (speedup 1.0000x reference)
#include <cuda_runtime.h>
#include <cuda_bf16.h>
#include <cuda_fp16.h>
#include <cstdint>

// ---------------- problem constants ----------------
#define N_NODES 100000
#define W_INF   256
#define W_OUTF  64
#define CCH     2
#define TTYPE   4
#define EDGES   800000
#define TE      (TTYPE*EDGES)          // 3,200,000
#define MTGT    20000
#define NCLS    4
#define BETA    0.5f
#define NB_SCAN 98                     // ceil(100000/1024)
#define KP      264                    // padded k-stride in halves (528B)
#define NTILE   1563                   // ceil(100000/64)
#define NSM     148

// ---------------- scratch (device globals: allocation-free) ----------------
__device__ __half g_Xh [N_NODES * 128];   // X_ fp16 (gemm output)
__device__ float  g_H2 [N_NODES * 64];    // after linear1+relu
__device__ float  g_y  [MTGT * 4];        // fallback y scratch
__device__ float  g_loss;
__device__ float  g_sc [8];               // (1-BETA)*softmax(conv_weight)[c][t]
__device__ __half g_Whl[65536];           // W fp16: [hi|lo], n-major k-contig [128][256]
__device__ __half g_Xi [(size_t)NTILE*64*256]; // X fp16, padded to tile grid (51MB)

// CSR build scratch
__device__ int   g_cnt [N_NODES];
__device__ int   g_offp[N_NODES];
__device__ int   g_bsum[128];
__device__ int   g_bsumx[128];
__device__ int   g_off [N_NODES + 1];
__device__ int   g_cur [N_NODES];
__device__ unsigned long long g_epk[TE]; // packed: low32 = col, high32 = half2(w0,w1)

// ---------------- mma helpers ----------------
#define MMA16816(d, a0,a1,a2,a3, b0,b1) \
    asm volatile("mma.sync.aligned.m16n8k16.row.col.f32.f16.f16.f32 " \
        "{%0,%1,%2,%3}, {%4,%5,%6,%7}, {%8,%9}, {%0,%1,%2,%3};" \
        : "+f"((d)[0]), "+f"((d)[1]), "+f"((d)[2]), "+f"((d)[3]) \
        : "r"(a0), "r"(a1), "r"(a2), "r"(a3), "r"(b0), "r"(b1))

#define LDSM4(r0,r1,r2,r3, addr) \
    asm volatile("ldmatrix.sync.aligned.m8n8.x4.shared.b16 {%0,%1,%2,%3}, [%4];" \
        : "=r"(r0), "=r"(r1), "=r"(r2), "=r"(r3) : "r"(addr))

// ---------------- prepX: X fp32 -> fp16 (padded) + W hi/lo split (blocks 0-31)
__global__ void k_prepX(const float* __restrict__ X, const float* __restrict__ Ws) {
    size_t i = (size_t)blockIdx.x * 256 + threadIdx.x;   // one float4 per thread
    if (i < (size_t)NTILE * 64 * 64) {
        size_t row = i >> 6;
        int q = (int)(i & 63);
        float4 v = make_float4(0.f, 0.f, 0.f, 0.f);
        if (row < N_NODES) v = *(const float4*)&X[row*256 + q*4];
        __half2 h0 = __floats2half2_rn(v.x, v.y);
        __half2 h1 = __floats2half2_rn(v.z, v.w);
        *(uint2*)&g_Xi[row*256 + q*4] = make_uint2(*(unsigned*)&h0, *(unsigned*)&h1);
    }
    if (blockIdx.x < 32) {
        const int idx = blockIdx.x * 256 + threadIdx.x;   // 8192 threads
        for (int j = idx; j < 32768; j += 8192) {
            int n = j >> 8, k = j & 255;
            int c = n >> 6, o = n & 63;
            float w = Ws[(c*256 + k)*64 + o];
            __half h = __float2half_rn(w);
            __half l = __float2half_rn(w - __half2float(h));
            g_Whl[n*256 + k]         = h;
            g_Whl[32768 + n*256 + k] = l;
        }
    }
}

// ---------------- zero hist + compute scales + zero loss (branch B head) ----
__global__ void k_zero(const float* __restrict__ cw) {
    int i = blockIdx.x * 256 + threadIdx.x;
    if (i < N_NODES) g_cnt[i] = 0;
    if (i == 0) {
        for (int c = 0; c < CCH; c++) {
            float m = -1e30f;
            for (int t = 0; t < TTYPE; t++) m = fmaxf(m, cw[c*TTYPE + t]);
            float e[TTYPE], s = 0.f;
            for (int t = 0; t < TTYPE; t++) { e[t] = expf(cw[c*TTYPE + t] - m); s += e[t]; }
            float inv = (1.0f - BETA) / s;
            for (int t = 0; t < TTYPE; t++) g_sc[c*TTYPE + t] = e[t] * inv;
        }
        g_loss = 0.f;
    }
}

// ---------------- histogram of destination rows ----------------
__global__ void k_hist(const int* __restrict__ ei) {
    const int t = blockIdx.y;
    const int e = blockIdx.x * 256 + threadIdx.x;
    if (e >= EDGES) return;
    int row = __ldg(&ei[(t*2 + 0)*EDGES + e]);
    atomicAdd(&g_cnt[row], 1);
}

// ---------------- scan stage 1 ----------------
__global__ void k_scan1() {
    __shared__ int s[256];
    const int tid = threadIdx.x;
    const int base = blockIdx.x * 1024 + tid * 4;
    int v0 = 0, v1 = 0, v2 = 0, v3 = 0;
    if (base + 3 < N_NODES) {
        int4 q = *(const int4*)&g_cnt[base];
        v0 = q.x; v1 = q.y; v2 = q.z; v3 = q.w;
    } else {
        if (base     < N_NODES) v0 = g_cnt[base];
        if (base + 1 < N_NODES) v1 = g_cnt[base + 1];
        if (base + 2 < N_NODES) v2 = g_cnt[base + 2];
        if (base + 3 < N_NODES) v3 = g_cnt[base + 3];
    }
    int tsum = v0 + v1 + v2 + v3;
    s[tid] = tsum;
    __syncthreads();
    for (int d = 1; d < 256; d <<= 1) {
        int t = 0;
        if (tid >= d) t = s[tid - d];
        __syncthreads();
        if (tid >= d) s[tid] += t;
        __syncthreads();
    }
    int excl = s[tid] - tsum;
    if (base     < N_NODES) g_offp[base]     = excl;           excl += v0;
    if (base + 1 < N_NODES) g_offp[base + 1] = excl;           excl += v1;
    if (base + 2 < N_NODES) g_offp[base + 2] = excl;           excl += v2;
    if (base + 3 < N_NODES) g_offp[base + 3] = excl;
    if (tid == 255) g_bsum[blockIdx.x] = s[255];
}

// ---------------- scan stage 2 ----------------
__global__ void k_scan2() {
    __shared__ int s[128];
    const int tid = threadIdx.x;
    int v = (tid < NB_SCAN) ? g_bsum[tid] : 0;
    s[tid] = v;
    __syncthreads();
    for (int d = 1; d < 128; d <<= 1) {
        int t = 0;
        if (tid >= d) t = s[tid - d];
        __syncthreads();
        if (tid >= d) s[tid] += t;
        __syncthreads();
    }
    g_bsumx[tid] = s[tid] - v;
}

// ---------------- scan stage 3 ----------------
__global__ void k_scan3() {
    int i = blockIdx.x * 256 + threadIdx.x;
    if (i < N_NODES) {
        int o = g_offp[i] + g_bsumx[i >> 10];
        g_off[i] = o;
        g_cur[i] = o;
    }
    if (i == 0) g_off[N_NODES] = TE;
}

// ---------------- persistent GEMM: g_Xh = fp16(xh @ (Whi + Wlo)) -------------
__global__ void __launch_bounds__(256, 1) k_gemm() {
    extern __shared__ __half sm[];
    __half* WHI = sm;                  // 128*264 = 33792 halves
    __half* WLO = sm + 33792;
    __half* XB0 = sm + 67584;          // 64*264 = 16896 halves
    __half* XB1 = sm + 84480;          // total 101376 halves = 202752 B

    const int tid = threadIdx.x, lane = tid & 31, wid = tid >> 5;

    // W copy (once per CTA lifetime)
    {
        const uint4* src = (const uint4*)g_Whl;   // 8192 uint4
        for (int i = tid; i < 8192; i += 256) {
            int hs = i >> 12;
            int j  = i & 4095;
            int r  = j >> 5, q = j & 31;
            __half* dst = hs ? WLO : WHI;
            *(uint4*)&dst[r*KP + q*8] = src[i];
        }
    }

    const int mt = wid & 3;             // m-tile (16 rows)
    const int nh = wid >> 2;            // n-half (64 cols)
    const int wr = mt * 16;
    const int arow = wr + (lane & 15);
    const int acolofs = (lane & 16) ? 8 : 0;
    const int brow = ((lane & 16) ? 8 : 0) + (lane & 7);
    const int bko  = (lane & 8) ? 8 : 0;

    // prefetch first tile into XB0
    {
        const __half* gs = &g_Xi[(size_t)blockIdx.x * 64 * 256];
        #pragma unroll
        for (int j = 0; j < 8; j++) {
            int idx = tid + j*256;           // 0..2047 16B-chunks
            int r = idx >> 5, c = idx & 31;
            uint32_t da = (uint32_t)__cvta_generic_to_shared(&XB0[r*KP + c*8]);
            asm volatile("cp.async.cg.shared.global [%0], [%1], 16;"
                         :: "r"(da), "l"(gs + r*256 + c*8));
        }
        asm volatile("cp.async.commit_group;");
    }
    __syncthreads();   // W visible to all

    int tile = blockIdx.x;
    for (int it = 0; tile < NTILE; it++, tile += NSM) {
        const int ntile = tile + NSM;
        __half* cur = (it & 1) ? XB1 : XB0;
        __half* nxt = (it & 1) ? XB0 : XB1;

        if (ntile < NTILE) {
            const __half* gs = &g_Xi[(size_t)ntile * 64 * 256];
            #pragma unroll
            for (int j = 0; j < 8; j++) {
                int idx = tid + j*256;
                int r = idx >> 5, c = idx & 31;
                uint32_t da = (uint32_t)__cvta_generic_to_shared(&nxt[r*KP + c*8]);
                asm volatile("cp.async.cg.shared.global [%0], [%1], 16;"
                             :: "r"(da), "l"(gs + r*256 + c*8));
            }
            asm volatile("cp.async.commit_group;");
            asm volatile("cp.async.wait_group 1;");
        } else {
            asm volatile("cp.async.wait_group 0;");
        }
        __syncthreads();

        float d[8][4];
        #pragma unroll
        for (int l = 0; l < 8; l++)
            #pragma unroll
            for (int j = 0; j < 4; j++) d[l][j] = 0.f;

        #pragma unroll 1
        for (int ks = 0; ks < 16; ks++) {
            uint32_t ah0, ah1, ah2, ah3;
            {
                int acol = ks*16 + acolofs;
                uint32_t aa = (uint32_t)__cvta_generic_to_shared(&cur[arow*KP + acol]);
                LDSM4(ah0, ah1, ah2, ah3, aa);
            }
            uint32_t bh[4][4], bl[4][4];
            #pragma unroll
            for (int p = 0; p < 4; p++) {
                int nrow = nh*64 + p*16 + brow;
                int kofs = ks*16 + bko;
                uint32_t ha = (uint32_t)__cvta_generic_to_shared(&WHI[nrow*KP + kofs]);
                uint32_t la = (uint32_t)__cvta_generic_to_shared(&WLO[nrow*KP + kofs]);
                LDSM4(bh[p][0], bh[p][1], bh[p][2], bh[p][3], ha);
                LDSM4(bl[p][0], bl[p][1], bl[p][2], bl[p][3], la);
            }
            #pragma unroll
            for (int l = 0; l < 8; l++) {
                int p = l >> 1, o = (l & 1) * 2;
                MMA16816(d[l], ah0, ah1, ah2, ah3, bh[p][o], bh[p][o+1]);
                MMA16816(d[l], ah0, ah1, ah2, ah3, bl[p][o], bl[p][o+1]);
            }
        }

        // epilogue: fp16 only
        const int row0 = tile * 64;
        const int er0 = row0 + wr + (lane >> 2);
        const int ec  = (lane & 3) * 2;
        #pragma unroll
        for (int l = 0; l < 8; l++) {
            int n = (nh*8 + l)*8 + ec;
            if (er0 < N_NODES) {
                __half2 hp = __floats2half2_rn(d[l][0], d[l][1]);
                *(unsigned*)&g_Xh[(size_t)er0*128 + n] = *(unsigned*)&hp;
            }
            if (er0 + 8 < N_NODES) {
                __half2 hp = __floats2half2_rn(d[l][2], d[l][3]);
                *(unsigned*)&g_Xh[(size_t)(er0+8)*128 + n] = *(unsigned*)&hp;
            }
        }
        __syncthreads();   // all reads of cur done before it is prefetched next iter
    }
}

// ---------------- bucket: CSR slots, pre-scaled fp16 weights (8B records) -----
__global__ void k_bucket(const int* __restrict__ ei, const float* __restrict__ ev) {
    const int t = blockIdx.y;
    const int e = blockIdx.x * 256 + threadIdx.x;
    if (e >= EDGES) return;
    int   row = __ldg(&ei[(t*2 + 0)*EDGES + e]);
    int   col = __ldg(&ei[(t*2 + 1)*EDGES + e]);
    float val = __ldg(&ev[t*EDGES + e]);
    int pos = atomicAdd(&g_cur[row], 1);
    __half2 w = __floats2half2_rn(val * g_sc[t], val * g_sc[4 + t]);
    g_epk[pos] = ((unsigned long long)(*(unsigned*)&w) << 32) | (unsigned)col;
}

// ---------------- fused gather+lin1: 64 nodes/block ---------------------------
// Phase 1: warp w gathers nodes node0+w*8 .. +7 (half-warp per edge), writes
// relu(BETA*xh + msgs) straight into lin1 staging smem. Phase 2: k_lin1 compute.
__global__ void __launch_bounds__(256) k_gl(const float* __restrict__ W1,
                                            const float* __restrict__ b1) {
    extern __shared__ float smf[];
    float4* W1q = (float4*)smf;         // 2048 float4 (32KB)
    float*  Hsb = smf + 8192;           // 8192 floats (32KB)

    const int tid = threadIdx.x, lane = tid & 31, wid = tid >> 5;

    // load W1 swizzled (read in phase 2, after the sync)
    for (int idx2 = tid; idx2 < 4096; idx2 += 256) {
        int jp = idx2 & 63, o = idx2 >> 6;
        float2 w = *(const float2*)&W1[o*128 + jp*2];
        int slot = jp*32 + ((o & 31) ^ (jp & 31));
        ((float2*)&W1q[slot])[o >> 5] = w;
    }

    const int half = lane >> 4;         // 0 or 1
    const int sub  = lane & 15;         // owns cols sub*8..sub*8+7
    float* HsW = Hsb + wid * 1024;
    const int node0 = blockIdx.x * 64 + wid * 8;

    // ---- phase 1: gather 8 nodes into HsW ----
    #pragma unroll 1
    for (int r = 0; r < 8; r++) {
        const int n = node0 + r;
        float acc[8];
        #pragma unroll
        for (int i = 0; i < 8; i++) acc[i] = 0.f;

        if (n < N_NODES) {
            const int s0 = __ldg(&g_off[n]);
            const int s1 = __ldg(&g_off[n + 1]);
            for (int e2 = s0; e2 < s1; e2 += 4) {
                const int eA = e2 + half;
                const int eB = e2 + half + 2;
                unsigned long long pA = (eA < s1) ? __ldg(&g_epk[eA]) : 0ull;
                unsigned long long pB = (eB < s1) ? __ldg(&g_epk[eB]) : 0ull;
                unsigned cA = (unsigned)pA & 0x1FFFFu;
                unsigned cB = (unsigned)pB & 0x1FFFFu;
                uint4 vA = __ldg((const uint4*)&g_Xh[(size_t)cA*128 + sub*8]);
                uint4 vB = __ldg((const uint4*)&g_Xh[(size_t)cB*128 + sub*8]);
                unsigned wAb = (unsigned)(pA >> 32);
                unsigned wBb = (unsigned)(pB >> 32);
                __half2 wA2 = *(__half2*)&wAb;
                __half2 wB2 = *(__half2*)&wBb;
                const bool ch1 = (sub >= 8);
                float wA = ch1 ? __high2float(wA2) : __low2float(wA2);
                float wB = ch1 ? __high2float(wB2) : __low2float(wB2);

                float2 a0 = __half22float2(*(__half2*)&vA.x);
                float2 a1 = __half22float2(*(__half2*)&vA.y);
                float2 a2 = __half22float2(*(__half2*)&vA.z);
                float2 a3 = __half22float2(*(__half2*)&vA.w);
                acc[0] = fmaf(a0.x, wA, acc[0]); acc[1] = fmaf(a0.y, wA, acc[1]);
                acc[2] = fmaf(a1.x, wA, acc[2]); acc[3] = fmaf(a1.y, wA, acc[3]);
                acc[4] = fmaf(a2.x, wA, acc[4]); acc[5] = fmaf(a2.y, wA, acc[5]);
                acc[6] = fmaf(a3.x, wA, acc[6]); acc[7] = fmaf(a3.y, wA, acc[7]);

                float2 b0 = __half22float2(*(__half2*)&vB.x);
                float2 b1v = __half22float2(*(__half2*)&vB.y);
                float2 b2 = __half22float2(*(__half2*)&vB.z);
                float2 b3 = __half22float2(*(__half2*)&vB.w);
                acc[0] = fmaf(b0.x, wB, acc[0]); acc[1] = fmaf(b0.y, wB, acc[1]);
                acc[2] = fmaf(b1v.x, wB, acc[2]); acc[3] = fmaf(b1v.y, wB, acc[3]);
                acc[4] = fmaf(b2.x, wB, acc[4]); acc[5] = fmaf(b2.y, wB, acc[5]);
                acc[6] = fmaf(b3.x, wB, acc[6]); acc[7] = fmaf(b3.y, wB, acc[7]);
            }

            #pragma unroll
            for (int i = 0; i < 8; i++)
                acc[i] += __shfl_xor_sync(0xffffffffu, acc[i], 16);

            if (half == 0) {
                uint4 xv = __ldg((const uint4*)&g_Xh[(size_t)n*128 + sub*8]);
                float2 x0 = __half22float2(*(__half2*)&xv.x);
                float2 x1 = __half22float2(*(__half2*)&xv.y);
                float2 x2 = __half22float2(*(__half2*)&xv.z);
                float2 x3 = __half22float2(*(__half2*)&xv.w);
                float4 o0, o1;
                o0.x = fmaxf(fmaf(BETA, x0.x, acc[0]), 0.f);
                o0.y = fmaxf(fmaf(BETA, x0.y, acc[1]), 0.f);
                o0.z = fmaxf(fmaf(BETA, x1.x, acc[2]), 0.f);
                o0.w = fmaxf(fmaf(BETA, x1.y, acc[3]), 0.f);
                o1.x = fmaxf(fmaf(BETA, x2.x, acc[4]), 0.f);
                o1.y = fmaxf(fmaf(BETA, x2.y, acc[5]), 0.f);
                o1.z = fmaxf(fmaf(BETA, x3.x, acc[6]), 0.f);
                o1.w = fmaxf(fmaf(BETA, x3.y, acc[7]), 0.f);
                *(float4*)&HsW[r*128 + sub*8]     = o0;
                *(float4*)&HsW[r*128 + sub*8 + 4] = o1;
            }
        } else if (half == 0) {
            float4 z = make_float4(0.f, 0.f, 0.f, 0.f);
            *(float4*)&HsW[r*128 + sub*8]     = z;
            *(float4*)&HsW[r*128 + sub*8 + 4] = z;
        }
    }
    __syncthreads();

    // ---- phase 2: lin1 on staged rows ----
    float acc0[8], acc1[8];
    #pragma unroll
    for (int r = 0; r < 8; r++) { acc0[r] = 0.f; acc1[r] = 0.f; }

    #pragma unroll 4
    for (int j2 = 0; j2 < 64; j2++) {
        float4 q = W1q[j2*32 + (lane ^ (j2 & 31))];
        #pragma unroll
        for (int r = 0; r < 8; r++) {
            float2 h = *(const float2*)&HsW[r*128 + j2*2];
            acc0[r] = fmaf(h.y, q.y, fmaf(h.x, q.x, acc0[r]));
            acc1[r] = fmaf(h.y, q.w, fmaf(h.x, q.z, acc1[r]));
        }
    }

    const float bb0 = __ldg(&b1[lane]);
    const float bb1 = __ldg(&b1[lane + 32]);
    #pragma unroll
    for (int r = 0; r < 8; r++) {
        int row = node0 + r;
        if (row < N_NODES) {
            g_H2[(size_t)row*64 + lane]      = fmaxf(acc0[r] + bb0, 0.f);
            g_H2[(size_t)row*64 + lane + 32] = fmaxf(acc1[r] + bb1, 0.f);
        }
    }
}

// ---------------- head: y + loss terms ----------------
__global__ void k_head(const float* __restrict__ lw, const float* __restrict__ lb,
                       const int* __restrict__ tx, const int* __restrict__ tg,
                       float* __restrict__ yout) {
    __shared__ float Wls[4*64 + 4];
    __shared__ float red[256];
    const int tid = threadIdx.x;
    for (int i = tid; i < 260; i += 256) Wls[i] = (i < 256) ? lw[i] : lb[i - 256];
    __syncthreads();

    const int i = blockIdx.x * 256 + tid;
    float lsum = 0.f;
    if (i < MTGT) {
        const int node = __ldg(&tx[i]);
        float l0 = Wls[256], l1 = Wls[257], l2 = Wls[258], l3 = Wls[259];
        const float* h = &g_H2[(size_t)node*64];
        #pragma unroll
        for (int k = 0; k < 64; k += 4) {
            float4 hv = *(const float4*)&h[k];
            l0 += hv.x*Wls[0*64+k] + hv.y*Wls[0*64+k+1] + hv.z*Wls[0*64+k+2] + hv.w*Wls[0*64+k+3];
            l1 += hv.x*Wls[1*64+k] + hv.y*Wls[1*64+k+1] + hv.z*Wls[1*64+k+2] + hv.w*Wls[1*64+k+3];
            l2 += hv.x*Wls[2*64+k] + hv.y*Wls[2*64+k+1] + hv.z*Wls[2*64+k+2] + hv.w*Wls[2*64+k+3];
            l3 += hv.x*Wls[3*64+k] + hv.y*Wls[3*64+k+1] + hv.z*Wls[3*64+k+2] + hv.w*Wls[3*64+k+3];
        }
        yout[i*4+0] = l0; yout[i*4+1] = l1; yout[i*4+2] = l2; yout[i*4+3] = l3;
        float m  = fmaxf(fmaxf(l0, l1), fmaxf(l2, l3));
        float se = expf(l0-m) + expf(l1-m) + expf(l2-m) + expf(l3-m);
        float lse = m + logf(se);
        int t = __ldg(&tg[i]);
        float lt = (t == 0) ? l0 : (t == 1) ? l1 : (t == 2) ? l2 : l3;
        lsum = lse - lt;
    }
    red[tid] = lsum;
    __syncthreads();
    #pragma unroll
    for (int s = 128; s > 0; s >>= 1) {
        if (tid < s) red[tid] += red[tid + s];
        __syncthreads();
    }
    if (tid == 0) atomicAdd(&g_loss, red[0]);
}

__global__ void k_fin(float* __restrict__ out, int write_loss) {
    if (write_loss) out[0] = g_loss / (float)MTGT;
}

// ---------------- launch ----------------
extern "C" void kernel_launch(void* const* d_in, const int* in_sizes, int n_in,
                              void* d_out, int out_size) {
    const float* X  = (const float*)d_in[0];
    const float* ev = (const float*)d_in[1];
    const float* Ws = (const float*)d_in[2];
    const float* cw = (const float*)d_in[3];
    const float* W1 = (const float*)d_in[4];
    const float* b1 = (const float*)d_in[5];
    const float* lw = (const float*)d_in[6];
    const float* lb = (const float*)d_in[7];
    const int*   ei = (const int*)d_in[8];
    const int*   tx = (const int*)d_in[9];
    const int*   tg = (const int*)d_in[10];
    float* out = (float*)d_out;

    float* yscratch = nullptr;
    cudaGetSymbolAddress((void**)&yscratch, g_y);

    float* yout;
    int write_loss;
    if (out_size == MTGT*4 + 1)      { yout = out + 1;  write_loss = 1; }
    else if (out_size == MTGT*4)     { yout = out;      write_loss = 0; }
    else                             { yout = yscratch; write_loss = 1; }

    static cudaStream_t s2 = nullptr;
    static cudaEvent_t ev_fork = nullptr, ev_join = nullptr;
    if (s2 == nullptr) {
        cudaStreamCreateWithFlags(&s2, cudaStreamNonBlocking);
        cudaEventCreateWithFlags(&ev_fork, cudaEventDisableTiming);
        cudaEventCreateWithFlags(&ev_join, cudaEventDisableTiming);
    }

    cudaEventRecord(ev_fork, 0);
    cudaStreamWaitEvent(s2, ev_fork, 0);

    // ---- default stream: X convert + W prep ----
    k_prepX<<<(NTILE*64*64 + 255)/256, 256>>>(X, Ws);

    // ---- branch B (s2): zero + scales ----
    dim3 eg((EDGES + 255)/256, TTYPE);
    k_zero<<<(N_NODES + 255)/256, 256, 0, s2>>>(cw);

    // ---- branch A (default): persistent GEMM ----
    const int gemm_smem = 101376 * sizeof(__half);   // 202752 B
    cudaFuncSetAttribute(k_gemm, cudaFuncAttributeMaxDynamicSharedMemorySize, gemm_smem);
    k_gemm<<<NSM, 256, gemm_smem>>>();

    // ---- branch B (s2): hist + scan + bucket ----
    k_hist<<<eg, 256, 0, s2>>>(ei);
    k_scan1<<<NB_SCAN, 256, 0, s2>>>();
    k_scan2<<<1, 128, 0, s2>>>();
    k_scan3<<<(N_NODES + 255)/256, 256, 0, s2>>>();
    k_bucket<<<eg, 256, 0, s2>>>(ei, ev);
    cudaEventRecord(ev_join, s2);

    // ---- join ----
    cudaStreamWaitEvent(0, ev_join, 0);

    // ---- fused gather + lin1 ----
    const int gl_smem = 65536;
    cudaFuncSetAttribute(k_gl, cudaFuncAttributeMaxDynamicSharedMemorySize, gl_smem);
    k_gl<<<NTILE, 256, gl_smem>>>(W1, b1);

    k_head<<<(MTGT + 255)/256, 256>>>(lw, lb, tx, tg, yout);
    k_fin<<<1, 1>>>(out, write_loss);
}

// round 16
// speedup vs baseline: 1.2164x; 1.2164x over previous
#include <cuda_runtime.h>
#include <cuda_bf16.h>
#include <cuda_fp16.h>
#include <cstdint>

// ---------------- problem constants ----------------
#define N_NODES 100000
#define W_INF   256
#define W_OUTF  64
#define CCH     2
#define TTYPE   4
#define EDGES   800000
#define TE      (TTYPE*EDGES)          // 3,200,000
#define MTGT    20000
#define NCLS    4
#define BETA    0.5f
#define NB_SCAN 98                     // ceil(100000/1024)
#define KP      264                    // padded k-stride in halves (528B)
#define NTILE   1563                   // ceil(100000/64)
#define NSM     148
#define NSPLIT  50048                  // gather/lin1 pipeline split (64-aligned)

// ---------------- scratch (device globals: allocation-free) ----------------
__device__ __half g_Xh [N_NODES * 128];   // X_ fp16 (gemm output)
__device__ float  g_Acc[N_NODES * 128];   // relu(BETA*X_ + (1-BETA)*scatter)
__device__ float  g_H2 [N_NODES * 64];    // after linear1+relu
__device__ float  g_y  [MTGT * 4];        // fallback y scratch
__device__ float  g_loss;
__device__ float  g_sc [8];               // (1-BETA)*softmax(conv_weight)[c][t]
__device__ __half g_Whl[65536];           // W fp16: [hi|lo], n-major k-contig [128][256]
__device__ __half g_Xi [(size_t)NTILE*64*256]; // X fp16, padded to tile grid (51MB)

// CSR build scratch
__device__ int   g_cnt [N_NODES];
__device__ int   g_offp[N_NODES];
__device__ int   g_bsum[128];
__device__ int   g_bsumx[128];
__device__ int   g_off [N_NODES + 1];
__device__ int   g_cur [N_NODES];
__device__ unsigned long long g_epk[TE]; // packed: low32 = col, high32 = half2(w0,w1)

// ---------------- mma helpers ----------------
#define MMA16816(d, a0,a1,a2,a3, b0,b1) \
    asm volatile("mma.sync.aligned.m16n8k16.row.col.f32.f16.f16.f32 " \
        "{%0,%1,%2,%3}, {%4,%5,%6,%7}, {%8,%9}, {%0,%1,%2,%3};" \
        : "+f"((d)[0]), "+f"((d)[1]), "+f"((d)[2]), "+f"((d)[3]) \
        : "r"(a0), "r"(a1), "r"(a2), "r"(a3), "r"(b0), "r"(b1))

#define LDSM4(r0,r1,r2,r3, addr) \
    asm volatile("ldmatrix.sync.aligned.m8n8.x4.shared.b16 {%0,%1,%2,%3}, [%4];" \
        : "=r"(r0), "=r"(r1), "=r"(r2), "=r"(r3) : "r"(addr))

// ---------------- prepX: X fp32 -> fp16 (padded) + W hi/lo split (blocks 0-31)
__global__ void k_prepX(const float* __restrict__ X, const float* __restrict__ Ws) {
    size_t i = (size_t)blockIdx.x * 256 + threadIdx.x;   // one float4 per thread
    if (i < (size_t)NTILE * 64 * 64) {
        size_t row = i >> 6;
        int q = (int)(i & 63);
        float4 v = make_float4(0.f, 0.f, 0.f, 0.f);
        if (row < N_NODES) v = *(const float4*)&X[row*256 + q*4];
        __half2 h0 = __floats2half2_rn(v.x, v.y);
        __half2 h1 = __floats2half2_rn(v.z, v.w);
        *(uint2*)&g_Xi[row*256 + q*4] = make_uint2(*(unsigned*)&h0, *(unsigned*)&h1);
    }
    if (blockIdx.x < 32) {
        const int idx = blockIdx.x * 256 + threadIdx.x;   // 8192 threads
        for (int j = idx; j < 32768; j += 8192) {
            int n = j >> 8, k = j & 255;
            int c = n >> 6, o = n & 63;
            float w = Ws[(c*256 + k)*64 + o];
            __half h = __float2half_rn(w);
            __half l = __float2half_rn(w - __half2float(h));
            g_Whl[n*256 + k]         = h;
            g_Whl[32768 + n*256 + k] = l;
        }
    }
}

// ---------------- zero hist + compute scales + zero loss (branch B head) ----
__global__ void k_zero(const float* __restrict__ cw) {
    int i = blockIdx.x * 256 + threadIdx.x;
    if (i < N_NODES) g_cnt[i] = 0;
    if (i == 0) {
        for (int c = 0; c < CCH; c++) {
            float m = -1e30f;
            for (int t = 0; t < TTYPE; t++) m = fmaxf(m, cw[c*TTYPE + t]);
            float e[TTYPE], s = 0.f;
            for (int t = 0; t < TTYPE; t++) { e[t] = expf(cw[c*TTYPE + t] - m); s += e[t]; }
            float inv = (1.0f - BETA) / s;
            for (int t = 0; t < TTYPE; t++) g_sc[c*TTYPE + t] = e[t] * inv;
        }
        g_loss = 0.f;
    }
}

// ---------------- histogram of destination rows ----------------
__global__ void k_hist(const int* __restrict__ ei) {
    const int t = blockIdx.y;
    const int e = blockIdx.x * 256 + threadIdx.x;
    if (e >= EDGES) return;
    int row = __ldg(&ei[(t*2 + 0)*EDGES + e]);
    atomicAdd(&g_cnt[row], 1);
}

// ---------------- scan stage 1 ----------------
__global__ void k_scan1() {
    __shared__ int s[256];
    const int tid = threadIdx.x;
    const int base = blockIdx.x * 1024 + tid * 4;
    int v0 = 0, v1 = 0, v2 = 0, v3 = 0;
    if (base + 3 < N_NODES) {
        int4 q = *(const int4*)&g_cnt[base];
        v0 = q.x; v1 = q.y; v2 = q.z; v3 = q.w;
    } else {
        if (base     < N_NODES) v0 = g_cnt[base];
        if (base + 1 < N_NODES) v1 = g_cnt[base + 1];
        if (base + 2 < N_NODES) v2 = g_cnt[base + 2];
        if (base + 3 < N_NODES) v3 = g_cnt[base + 3];
    }
    int tsum = v0 + v1 + v2 + v3;
    s[tid] = tsum;
    __syncthreads();
    for (int d = 1; d < 256; d <<= 1) {
        int t = 0;
        if (tid >= d) t = s[tid - d];
        __syncthreads();
        if (tid >= d) s[tid] += t;
        __syncthreads();
    }
    int excl = s[tid] - tsum;
    if (base     < N_NODES) g_offp[base]     = excl;           excl += v0;
    if (base + 1 < N_NODES) g_offp[base + 1] = excl;           excl += v1;
    if (base + 2 < N_NODES) g_offp[base + 2] = excl;           excl += v2;
    if (base + 3 < N_NODES) g_offp[base + 3] = excl;
    if (tid == 255) g_bsum[blockIdx.x] = s[255];
}

// ---------------- scan stage 2 ----------------
__global__ void k_scan2() {
    __shared__ int s[128];
    const int tid = threadIdx.x;
    int v = (tid < NB_SCAN) ? g_bsum[tid] : 0;
    s[tid] = v;
    __syncthreads();
    for (int d = 1; d < 128; d <<= 1) {
        int t = 0;
        if (tid >= d) t = s[tid - d];
        __syncthreads();
        if (tid >= d) s[tid] += t;
        __syncthreads();
    }
    g_bsumx[tid] = s[tid] - v;
}

// ---------------- scan stage 3 ----------------
__global__ void k_scan3() {
    int i = blockIdx.x * 256 + threadIdx.x;
    if (i < N_NODES) {
        int o = g_offp[i] + g_bsumx[i >> 10];
        g_off[i] = o;
        g_cur[i] = o;
    }
    if (i == 0) g_off[N_NODES] = TE;
}

// ---------------- persistent GEMM: g_Xh = fp16(xh @ (Whi + Wlo)) -------------
__global__ void __launch_bounds__(256, 1) k_gemm() {
    extern __shared__ __half sm[];
    __half* WHI = sm;                  // 128*264 = 33792 halves
    __half* WLO = sm + 33792;
    __half* XB0 = sm + 67584;          // 64*264 = 16896 halves
    __half* XB1 = sm + 84480;          // total 101376 halves = 202752 B

    const int tid = threadIdx.x, lane = tid & 31, wid = tid >> 5;

    // W copy (once per CTA lifetime)
    {
        const uint4* src = (const uint4*)g_Whl;   // 8192 uint4
        for (int i = tid; i < 8192; i += 256) {
            int hs = i >> 12;
            int j  = i & 4095;
            int r  = j >> 5, q = j & 31;
            __half* dst = hs ? WLO : WHI;
            *(uint4*)&dst[r*KP + q*8] = src[i];
        }
    }

    const int mt = wid & 3;             // m-tile (16 rows)
    const int nh = wid >> 2;            // n-half (64 cols)
    const int wr = mt * 16;
    const int arow = wr + (lane & 15);
    const int acolofs = (lane & 16) ? 8 : 0;
    const int brow = ((lane & 16) ? 8 : 0) + (lane & 7);
    const int bko  = (lane & 8) ? 8 : 0;

    // prefetch first tile into XB0
    {
        const __half* gs = &g_Xi[(size_t)blockIdx.x * 64 * 256];
        #pragma unroll
        for (int j = 0; j < 8; j++) {
            int idx = tid + j*256;           // 0..2047 16B-chunks
            int r = idx >> 5, c = idx & 31;
            uint32_t da = (uint32_t)__cvta_generic_to_shared(&XB0[r*KP + c*8]);
            asm volatile("cp.async.cg.shared.global [%0], [%1], 16;"
                         :: "r"(da), "l"(gs + r*256 + c*8));
        }
        asm volatile("cp.async.commit_group;");
    }
    __syncthreads();   // W visible to all

    int tile = blockIdx.x;
    for (int it = 0; tile < NTILE; it++, tile += NSM) {
        const int ntile = tile + NSM;
        __half* cur = (it & 1) ? XB1 : XB0;
        __half* nxt = (it & 1) ? XB0 : XB1;

        if (ntile < NTILE) {
            const __half* gs = &g_Xi[(size_t)ntile * 64 * 256];
            #pragma unroll
            for (int j = 0; j < 8; j++) {
                int idx = tid + j*256;
                int r = idx >> 5, c = idx & 31;
                uint32_t da = (uint32_t)__cvta_generic_to_shared(&nxt[r*KP + c*8]);
                asm volatile("cp.async.cg.shared.global [%0], [%1], 16;"
                             :: "r"(da), "l"(gs + r*256 + c*8));
            }
            asm volatile("cp.async.commit_group;");
            asm volatile("cp.async.wait_group 1;");
        } else {
            asm volatile("cp.async.wait_group 0;");
        }
        __syncthreads();

        float d[8][4];
        #pragma unroll
        for (int l = 0; l < 8; l++)
            #pragma unroll
            for (int j = 0; j < 4; j++) d[l][j] = 0.f;

        #pragma unroll 1
        for (int ks = 0; ks < 16; ks++) {
            uint32_t ah0, ah1, ah2, ah3;
            {
                int acol = ks*16 + acolofs;
                uint32_t aa = (uint32_t)__cvta_generic_to_shared(&cur[arow*KP + acol]);
                LDSM4(ah0, ah1, ah2, ah3, aa);
            }
            uint32_t bh[4][4], bl[4][4];
            #pragma unroll
            for (int p = 0; p < 4; p++) {
                int nrow = nh*64 + p*16 + brow;
                int kofs = ks*16 + bko;
                uint32_t ha = (uint32_t)__cvta_generic_to_shared(&WHI[nrow*KP + kofs]);
                uint32_t la = (uint32_t)__cvta_generic_to_shared(&WLO[nrow*KP + kofs]);
                LDSM4(bh[p][0], bh[p][1], bh[p][2], bh[p][3], ha);
                LDSM4(bl[p][0], bl[p][1], bl[p][2], bl[p][3], la);
            }
            #pragma unroll
            for (int l = 0; l < 8; l++) {
                int p = l >> 1, o = (l & 1) * 2;
                MMA16816(d[l], ah0, ah1, ah2, ah3, bh[p][o], bh[p][o+1]);
                MMA16816(d[l], ah0, ah1, ah2, ah3, bl[p][o], bl[p][o+1]);
            }
        }

        // epilogue: fp16 only
        const int row0 = tile * 64;
        const int er0 = row0 + wr + (lane >> 2);
        const int ec  = (lane & 3) * 2;
        #pragma unroll
        for (int l = 0; l < 8; l++) {
            int n = (nh*8 + l)*8 + ec;
            if (er0 < N_NODES) {
                __half2 hp = __floats2half2_rn(d[l][0], d[l][1]);
                *(unsigned*)&g_Xh[(size_t)er0*128 + n] = *(unsigned*)&hp;
            }
            if (er0 + 8 < N_NODES) {
                __half2 hp = __floats2half2_rn(d[l][2], d[l][3]);
                *(unsigned*)&g_Xh[(size_t)(er0+8)*128 + n] = *(unsigned*)&hp;
            }
        }
        __syncthreads();   // all reads of cur done before it is prefetched next iter
    }
}

// ---------------- bucket: CSR slots, pre-scaled fp16 weights (8B records) -----
__global__ void k_bucket(const int* __restrict__ ei, const float* __restrict__ ev) {
    const int t = blockIdx.y;
    const int e = blockIdx.x * 256 + threadIdx.x;
    if (e >= EDGES) return;
    int   row = __ldg(&ei[(t*2 + 0)*EDGES + e]);
    int   col = __ldg(&ei[(t*2 + 1)*EDGES + e]);
    float val = __ldg(&ev[t*EDGES + e]);
    int pos = atomicAdd(&g_cur[row], 1);
    __half2 w = __floats2half2_rn(val * g_sc[t], val * g_sc[4 + t]);
    g_epk[pos] = ((unsigned long long)(*(unsigned*)&w) << 32) | (unsigned)col;
}

// ---------------- gather: half-warp per edge, 8 edges/warp-iter ---------------
__global__ void __launch_bounds__(256) k_gather(int n0, int n1) {
    const int lane = threadIdx.x & 31;
    const int half = lane >> 4;         // 0 or 1
    const int sub  = lane & 15;         // owns cols sub*8..sub*8+7
    const int n = n0 + blockIdx.x * 8 + (threadIdx.x >> 5);
    if (n >= n1) return;

    const int s0 = __ldg(&g_off[n]);
    const int s1 = __ldg(&g_off[n + 1]);

    float acc[8];
    #pragma unroll
    for (int i = 0; i < 8; i++) acc[i] = 0.f;
    const bool ch1 = (sub >= 8);

    for (int e2 = s0; e2 < s1; e2 += 8) {
        const int eA = e2 + half;
        const int eB = eA + 2;
        const int eC = eA + 4;
        const int eD = eA + 6;
        unsigned long long pA = (eA < s1) ? __ldg(&g_epk[eA]) : 0ull;
        unsigned long long pB = (eB < s1) ? __ldg(&g_epk[eB]) : 0ull;
        unsigned long long pC = (eC < s1) ? __ldg(&g_epk[eC]) : 0ull;
        unsigned long long pD = (eD < s1) ? __ldg(&g_epk[eD]) : 0ull;
        unsigned cA = (unsigned)pA & 0x1FFFFu;
        unsigned cB = (unsigned)pB & 0x1FFFFu;
        unsigned cC = (unsigned)pC & 0x1FFFFu;
        unsigned cD = (unsigned)pD & 0x1FFFFu;
        uint4 vA = __ldg((const uint4*)&g_Xh[(size_t)cA*128 + sub*8]);
        uint4 vB = __ldg((const uint4*)&g_Xh[(size_t)cB*128 + sub*8]);
        uint4 vC = __ldg((const uint4*)&g_Xh[(size_t)cC*128 + sub*8]);
        uint4 vD = __ldg((const uint4*)&g_Xh[(size_t)cD*128 + sub*8]);
        unsigned wAb = (unsigned)(pA >> 32);
        unsigned wBb = (unsigned)(pB >> 32);
        unsigned wCb = (unsigned)(pC >> 32);
        unsigned wDb = (unsigned)(pD >> 32);
        __half2 wA2 = *(__half2*)&wAb;
        __half2 wB2 = *(__half2*)&wBb;
        __half2 wC2 = *(__half2*)&wCb;
        __half2 wD2 = *(__half2*)&wDb;
        float wA = ch1 ? __high2float(wA2) : __low2float(wA2);
        float wB = ch1 ? __high2float(wB2) : __low2float(wB2);
        float wC = ch1 ? __high2float(wC2) : __low2float(wC2);
        float wD = ch1 ? __high2float(wD2) : __low2float(wD2);

        {
            float2 a0 = __half22float2(*(__half2*)&vA.x);
            float2 a1 = __half22float2(*(__half2*)&vA.y);
            float2 a2 = __half22float2(*(__half2*)&vA.z);
            float2 a3 = __half22float2(*(__half2*)&vA.w);
            acc[0] = fmaf(a0.x, wA, acc[0]); acc[1] = fmaf(a0.y, wA, acc[1]);
            acc[2] = fmaf(a1.x, wA, acc[2]); acc[3] = fmaf(a1.y, wA, acc[3]);
            acc[4] = fmaf(a2.x, wA, acc[4]); acc[5] = fmaf(a2.y, wA, acc[5]);
            acc[6] = fmaf(a3.x, wA, acc[6]); acc[7] = fmaf(a3.y, wA, acc[7]);
        }
        {
            float2 b0 = __half22float2(*(__half2*)&vB.x);
            float2 b1 = __half22float2(*(__half2*)&vB.y);
            float2 b2 = __half22float2(*(__half2*)&vB.z);
            float2 b3 = __half22float2(*(__half2*)&vB.w);
            acc[0] = fmaf(b0.x, wB, acc[0]); acc[1] = fmaf(b0.y, wB, acc[1]);
            acc[2] = fmaf(b1.x, wB, acc[2]); acc[3] = fmaf(b1.y, wB, acc[3]);
            acc[4] = fmaf(b2.x, wB, acc[4]); acc[5] = fmaf(b2.y, wB, acc[5]);
            acc[6] = fmaf(b3.x, wB, acc[6]); acc[7] = fmaf(b3.y, wB, acc[7]);
        }
        {
            float2 c0 = __half22float2(*(__half2*)&vC.x);
            float2 c1 = __half22float2(*(__half2*)&vC.y);
            float2 c2 = __half22float2(*(__half2*)&vC.z);
            float2 c3 = __half22float2(*(__half2*)&vC.w);
            acc[0] = fmaf(c0.x, wC, acc[0]); acc[1] = fmaf(c0.y, wC, acc[1]);
            acc[2] = fmaf(c1.x, wC, acc[2]); acc[3] = fmaf(c1.y, wC, acc[3]);
            acc[4] = fmaf(c2.x, wC, acc[4]); acc[5] = fmaf(c2.y, wC, acc[5]);
            acc[6] = fmaf(c3.x, wC, acc[6]); acc[7] = fmaf(c3.y, wC, acc[7]);
        }
        {
            float2 d0 = __half22float2(*(__half2*)&vD.x);
            float2 d1 = __half22float2(*(__half2*)&vD.y);
            float2 d2 = __half22float2(*(__half2*)&vD.z);
            float2 d3 = __half22float2(*(__half2*)&vD.w);
            acc[0] = fmaf(d0.x, wD, acc[0]); acc[1] = fmaf(d0.y, wD, acc[1]);
            acc[2] = fmaf(d1.x, wD, acc[2]); acc[3] = fmaf(d1.y, wD, acc[3]);
            acc[4] = fmaf(d2.x, wD, acc[4]); acc[5] = fmaf(d2.y, wD, acc[5]);
            acc[6] = fmaf(d3.x, wD, acc[6]); acc[7] = fmaf(d3.y, wD, acc[7]);
        }
    }

    // combine the two half-warp accumulators
    #pragma unroll
    for (int i = 0; i < 8; i++)
        acc[i] += __shfl_xor_sync(0xffffffffu, acc[i], 16);

    if (half == 0) {
        uint4 xv = __ldg((const uint4*)&g_Xh[(size_t)n*128 + sub*8]);
        float2 x0 = __half22float2(*(__half2*)&xv.x);
        float2 x1 = __half22float2(*(__half2*)&xv.y);
        float2 x2 = __half22float2(*(__half2*)&xv.z);
        float2 x3 = __half22float2(*(__half2*)&xv.w);
        float4 o0, o1;
        o0.x = fmaxf(fmaf(BETA, x0.x, acc[0]), 0.f);
        o0.y = fmaxf(fmaf(BETA, x0.y, acc[1]), 0.f);
        o0.z = fmaxf(fmaf(BETA, x1.x, acc[2]), 0.f);
        o0.w = fmaxf(fmaf(BETA, x1.y, acc[3]), 0.f);
        o1.x = fmaxf(fmaf(BETA, x2.x, acc[4]), 0.f);
        o1.y = fmaxf(fmaf(BETA, x2.y, acc[5]), 0.f);
        o1.z = fmaxf(fmaf(BETA, x3.x, acc[6]), 0.f);
        o1.w = fmaxf(fmaf(BETA, x3.y, acc[7]), 0.f);
        float* dst = &g_Acc[(size_t)n*128 + sub*8];
        *(float4*)dst       = o0;
        *(float4*)(dst + 4) = o1;
    }
}

// ---------------- lin1: H2 = relu(Acc @ W1^T + b1), rows [base, base+grid*64) -
__global__ void __launch_bounds__(256) k_lin1(const float* __restrict__ W1,
                                              const float* __restrict__ b1,
                                              int row_base) {
    extern __shared__ float smf[];
    float4* W1q = (float4*)smf;         // 2048 float4 (32KB)
    float*  Hsb = smf + 8192;           // 8192 floats (32KB)

    const int tid = threadIdx.x, lane = tid & 31, wid = tid >> 5;

    for (int idx2 = tid; idx2 < 4096; idx2 += 256) {
        int jp = idx2 & 63, o = idx2 >> 6;
        float2 w = *(const float2*)&W1[o*128 + jp*2];
        int slot = jp*32 + ((o & 31) ^ (jp & 31));
        ((float2*)&W1q[slot])[o >> 5] = w;
    }

    float* HsW = Hsb + wid * 1024;
    const int row0 = row_base + blockIdx.x * 64 + wid * 8;
    #pragma unroll
    for (int r = 0; r < 8; r++) {
        int row = row0 + r;
        float4 v = make_float4(0.f, 0.f, 0.f, 0.f);
        if (row < N_NODES) v = *(const float4*)&g_Acc[(size_t)row*128 + lane*4];
        *(float4*)&HsW[r*128 + lane*4] = v;
    }
    __syncthreads();

    float acc0[8], acc1[8];
    #pragma unroll
    for (int r = 0; r < 8; r++) { acc0[r] = 0.f; acc1[r] = 0.f; }

    #pragma unroll 4
    for (int j2 = 0; j2 < 64; j2++) {
        float4 q = W1q[j2*32 + (lane ^ (j2 & 31))];
        #pragma unroll
        for (int r = 0; r < 8; r++) {
            float2 h = *(const float2*)&HsW[r*128 + j2*2];
            acc0[r] = fmaf(h.y, q.y, fmaf(h.x, q.x, acc0[r]));
            acc1[r] = fmaf(h.y, q.w, fmaf(h.x, q.z, acc1[r]));
        }
    }

    const float bb0 = __ldg(&b1[lane]);
    const float bb1 = __ldg(&b1[lane + 32]);
    #pragma unroll
    for (int r = 0; r < 8; r++) {
        int row = row0 + r;
        if (row < N_NODES) {
            g_H2[(size_t)row*64 + lane]      = fmaxf(acc0[r] + bb0, 0.f);
            g_H2[(size_t)row*64 + lane + 32] = fmaxf(acc1[r] + bb1, 0.f);
        }
    }
}

// ---------------- head: y + loss terms ----------------
__global__ void k_head(const float* __restrict__ lw, const float* __restrict__ lb,
                       const int* __restrict__ tx, const int* __restrict__ tg,
                       float* __restrict__ yout) {
    __shared__ float Wls[4*64 + 4];
    __shared__ float red[256];
    const int tid = threadIdx.x;
    for (int i = tid; i < 260; i += 256) Wls[i] = (i < 256) ? lw[i] : lb[i - 256];
    __syncthreads();

    const int i = blockIdx.x * 256 + tid;
    float lsum = 0.f;
    if (i < MTGT) {
        const int node = __ldg(&tx[i]);
        float l0 = Wls[256], l1 = Wls[257], l2 = Wls[258], l3 = Wls[259];
        const float* h = &g_H2[(size_t)node*64];
        #pragma unroll
        for (int k = 0; k < 64; k += 4) {
            float4 hv = *(const float4*)&h[k];
            l0 += hv.x*Wls[0*64+k] + hv.y*Wls[0*64+k+1] + hv.z*Wls[0*64+k+2] + hv.w*Wls[0*64+k+3];
            l1 += hv.x*Wls[1*64+k] + hv.y*Wls[1*64+k+1] + hv.z*Wls[1*64+k+2] + hv.w*Wls[1*64+k+3];
            l2 += hv.x*Wls[2*64+k] + hv.y*Wls[2*64+k+1] + hv.z*Wls[2*64+k+2] + hv.w*Wls[2*64+k+3];
            l3 += hv.x*Wls[3*64+k] + hv.y*Wls[3*64+k+1] + hv.z*Wls[3*64+k+2] + hv.w*Wls[3*64+k+3];
        }
        yout[i*4+0] = l0; yout[i*4+1] = l1; yout[i*4+2] = l2; yout[i*4+3] = l3;
        float m  = fmaxf(fmaxf(l0, l1), fmaxf(l2, l3));
        float se = expf(l0-m) + expf(l1-m) + expf(l2-m) + expf(l3-m);
        float lse = m + logf(se);
        int t = __ldg(&tg[i]);
        float lt = (t == 0) ? l0 : (t == 1) ? l1 : (t == 2) ? l2 : l3;
        lsum = lse - lt;
    }
    red[tid] = lsum;
    __syncthreads();
    #pragma unroll
    for (int s = 128; s > 0; s >>= 1) {
        if (tid < s) red[tid] += red[tid + s];
        __syncthreads();
    }
    if (tid == 0) atomicAdd(&g_loss, red[0]);
}

__global__ void k_fin(float* __restrict__ out, int write_loss) {
    if (write_loss) out[0] = g_loss / (float)MTGT;
}

// ---------------- launch ----------------
extern "C" void kernel_launch(void* const* d_in, const int* in_sizes, int n_in,
                              void* d_out, int out_size) {
    const float* X  = (const float*)d_in[0];
    const float* ev = (const float*)d_in[1];
    const float* Ws = (const float*)d_in[2];
    const float* cw = (const float*)d_in[3];
    const float* W1 = (const float*)d_in[4];
    const float* b1 = (const float*)d_in[5];
    const float* lw = (const float*)d_in[6];
    const float* lb = (const float*)d_in[7];
    const int*   ei = (const int*)d_in[8];
    const int*   tx = (const int*)d_in[9];
    const int*   tg = (const int*)d_in[10];
    float* out = (float*)d_out;

    float* yscratch = nullptr;
    cudaGetSymbolAddress((void**)&yscratch, g_y);

    float* yout;
    int write_loss;
    if (out_size == MTGT*4 + 1)      { yout = out + 1;  write_loss = 1; }
    else if (out_size == MTGT*4)     { yout = out;      write_loss = 0; }
    else                             { yout = yscratch; write_loss = 1; }

    static cudaStream_t s2 = nullptr;
    static cudaEvent_t ev_fork = nullptr, ev_join = nullptr, ev_gA = nullptr, ev_l1 = nullptr;
    if (s2 == nullptr) {
        cudaStreamCreateWithFlags(&s2, cudaStreamNonBlocking);
        cudaEventCreateWithFlags(&ev_fork, cudaEventDisableTiming);
        cudaEventCreateWithFlags(&ev_join, cudaEventDisableTiming);
        cudaEventCreateWithFlags(&ev_gA, cudaEventDisableTiming);
        cudaEventCreateWithFlags(&ev_l1, cudaEventDisableTiming);
    }

    cudaEventRecord(ev_fork, 0);
    cudaStreamWaitEvent(s2, ev_fork, 0);

    // ---- default stream: X convert + W prep ----
    k_prepX<<<(NTILE*64*64 + 255)/256, 256>>>(X, Ws);

    // ---- branch B (s2): zero + scales ----
    dim3 eg((EDGES + 255)/256, TTYPE);
    k_zero<<<(N_NODES + 255)/256, 256, 0, s2>>>(cw);

    // ---- branch A (default): persistent GEMM ----
    const int gemm_smem = 101376 * sizeof(__half);   // 202752 B
    cudaFuncSetAttribute(k_gemm, cudaFuncAttributeMaxDynamicSharedMemorySize, gemm_smem);
    k_gemm<<<NSM, 256, gemm_smem>>>();

    // ---- branch B (s2): hist + scan + bucket ----
    k_hist<<<eg, 256, 0, s2>>>(ei);
    k_scan1<<<NB_SCAN, 256, 0, s2>>>();
    k_scan2<<<1, 128, 0, s2>>>();
    k_scan3<<<(N_NODES + 255)/256, 256, 0, s2>>>();
    k_bucket<<<eg, 256, 0, s2>>>(ei, ev);
    cudaEventRecord(ev_join, s2);

    // ---- join ----
    cudaStreamWaitEvent(0, ev_join, 0);

    const int lin1_smem = 65536;
    cudaFuncSetAttribute(k_lin1, cudaFuncAttributeMaxDynamicSharedMemorySize, lin1_smem);

    // ---- pipelined gather/lin1 ----
    k_gather<<<NSPLIT/8, 256>>>(0, NSPLIT);                       // gather A
    cudaEventRecord(ev_gA, 0);
    cudaStreamWaitEvent(s2, ev_gA, 0);
    k_lin1<<<NSPLIT/64, 256, lin1_smem, s2>>>(W1, b1, 0);         // lin1 A ∥ gather B
    cudaEventRecord(ev_l1, s2);
    k_gather<<<(N_NODES - NSPLIT + 7)/8, 256>>>(NSPLIT, N_NODES); // gather B
    k_lin1<<<(N_NODES - NSPLIT + 63)/64, 256, lin1_smem>>>(W1, b1, NSPLIT); // lin1 B
    cudaStreamWaitEvent(0, ev_l1, 0);

    k_head<<<(MTGT + 255)/256, 256>>>(lw, lb, tx, tg, yout);
    k_fin<<<1, 1>>>(out, write_loss);
}

// round 17
// speedup vs baseline: 1.3576x; 1.1161x over previous
#include <cuda_runtime.h>
#include <cuda_bf16.h>
#include <cuda_fp16.h>
#include <cstdint>

// ---------------- problem constants ----------------
#define N_NODES 100000
#define W_INF   256
#define W_OUTF  64
#define CCH     2
#define TTYPE   4
#define EDGES   800000
#define TE      (TTYPE*EDGES)          // 3,200,000
#define MTGT    20000
#define NCLS    4
#define BETA    0.5f
#define NB_SCAN 98                     // ceil(100000/1024)
#define KP      264                    // padded k-stride (gemm), halves
#define KP2     136                    // padded k-stride (lin1), halves
#define NTILE   1563                   // ceil(100000/64)
#define NSM     148
#define NSPLIT  50048                  // gather/lin1 pipeline split (64-aligned)

// ---------------- scratch (device globals: allocation-free) ----------------
__device__ __half g_Xh  [N_NODES * 128];  // X_ fp16 (gemm output)
__device__ __half g_AccH[N_NODES * 128];  // relu(BETA*X_ + msgs), fp16
__device__ float  g_H2  [N_NODES * 64];   // after linear1+relu
__device__ float  g_y   [MTGT * 4];       // fallback y scratch
__device__ float  g_loss;
__device__ float  g_sc  [8];              // (1-BETA)*softmax(conv_weight)[c][t]
__device__ __half g_Whl [65536];          // W fp16: [hi|lo], n-major k-contig [128][256]
__device__ __half g_W1hl[16384];          // W1 fp16: [hi|lo], [64][128]
__device__ __half g_Xi  [(size_t)NTILE*64*256]; // X fp16, padded to tile grid (51MB)

// CSR build scratch
__device__ int   g_cnt [N_NODES];
__device__ int   g_offp[N_NODES];
__device__ int   g_bsum[128];
__device__ int   g_bsumx[128];
__device__ int   g_off [N_NODES + 1];
__device__ int   g_cur [N_NODES];
__device__ unsigned long long g_epk[TE]; // packed: low32 = col, high32 = half2(w0,w1)

// ---------------- mma helpers ----------------
#define MMA16816(d, a0,a1,a2,a3, b0,b1) \
    asm volatile("mma.sync.aligned.m16n8k16.row.col.f32.f16.f16.f32 " \
        "{%0,%1,%2,%3}, {%4,%5,%6,%7}, {%8,%9}, {%0,%1,%2,%3};" \
        : "+f"((d)[0]), "+f"((d)[1]), "+f"((d)[2]), "+f"((d)[3]) \
        : "r"(a0), "r"(a1), "r"(a2), "r"(a3), "r"(b0), "r"(b1))

#define LDSM4(r0,r1,r2,r3, addr) \
    asm volatile("ldmatrix.sync.aligned.m8n8.x4.shared.b16 {%0,%1,%2,%3}, [%4];" \
        : "=r"(r0), "=r"(r1), "=r"(r2), "=r"(r3) : "r"(addr))

// ---------------- prepX: X fp32->fp16 + W,W1 hi/lo splits (blocks 0-31) ------
__global__ void k_prepX(const float* __restrict__ X, const float* __restrict__ Ws,
                        const float* __restrict__ W1) {
    size_t i = (size_t)blockIdx.x * 256 + threadIdx.x;
    if (i < (size_t)NTILE * 64 * 64) {
        size_t row = i >> 6;
        int q = (int)(i & 63);
        float4 v = make_float4(0.f, 0.f, 0.f, 0.f);
        if (row < N_NODES) v = *(const float4*)&X[row*256 + q*4];
        __half2 h0 = __floats2half2_rn(v.x, v.y);
        __half2 h1 = __floats2half2_rn(v.z, v.w);
        *(uint2*)&g_Xi[row*256 + q*4] = make_uint2(*(unsigned*)&h0, *(unsigned*)&h1);
    }
    if (blockIdx.x < 32) {
        const int idx = blockIdx.x * 256 + threadIdx.x;   // 8192 threads
        for (int j = idx; j < 32768; j += 8192) {
            int n = j >> 8, k = j & 255;
            int c = n >> 6, o = n & 63;
            float w = Ws[(c*256 + k)*64 + o];
            __half h = __float2half_rn(w);
            __half l = __float2half_rn(w - __half2float(h));
            g_Whl[n*256 + k]         = h;
            g_Whl[32768 + n*256 + k] = l;
        }
        // W1 split: [64][128]
        {
            int j = idx;   // exactly 8192 elements
            float w = W1[j];
            __half h = __float2half_rn(w);
            __half l = __float2half_rn(w - __half2float(h));
            g_W1hl[j]        = h;
            g_W1hl[8192 + j] = l;
        }
    }
}

// ---------------- zero hist + compute scales + zero loss ----------------
__global__ void k_zero(const float* __restrict__ cw) {
    int i = blockIdx.x * 256 + threadIdx.x;
    if (i < N_NODES) g_cnt[i] = 0;
    if (i == 0) {
        for (int c = 0; c < CCH; c++) {
            float m = -1e30f;
            for (int t = 0; t < TTYPE; t++) m = fmaxf(m, cw[c*TTYPE + t]);
            float e[TTYPE], s = 0.f;
            for (int t = 0; t < TTYPE; t++) { e[t] = expf(cw[c*TTYPE + t] - m); s += e[t]; }
            float inv = (1.0f - BETA) / s;
            for (int t = 0; t < TTYPE; t++) g_sc[c*TTYPE + t] = e[t] * inv;
        }
        g_loss = 0.f;
    }
}

// ---------------- histogram of destination rows ----------------
__global__ void k_hist(const int* __restrict__ ei) {
    const int t = blockIdx.y;
    const int e = blockIdx.x * 256 + threadIdx.x;
    if (e >= EDGES) return;
    int row = __ldg(&ei[(t*2 + 0)*EDGES + e]);
    atomicAdd(&g_cnt[row], 1);
}

// ---------------- scan stage 1 ----------------
__global__ void k_scan1() {
    __shared__ int s[256];
    const int tid = threadIdx.x;
    const int base = blockIdx.x * 1024 + tid * 4;
    int v0 = 0, v1 = 0, v2 = 0, v3 = 0;
    if (base + 3 < N_NODES) {
        int4 q = *(const int4*)&g_cnt[base];
        v0 = q.x; v1 = q.y; v2 = q.z; v3 = q.w;
    } else {
        if (base     < N_NODES) v0 = g_cnt[base];
        if (base + 1 < N_NODES) v1 = g_cnt[base + 1];
        if (base + 2 < N_NODES) v2 = g_cnt[base + 2];
        if (base + 3 < N_NODES) v3 = g_cnt[base + 3];
    }
    int tsum = v0 + v1 + v2 + v3;
    s[tid] = tsum;
    __syncthreads();
    for (int d = 1; d < 256; d <<= 1) {
        int t = 0;
        if (tid >= d) t = s[tid - d];
        __syncthreads();
        if (tid >= d) s[tid] += t;
        __syncthreads();
    }
    int excl = s[tid] - tsum;
    if (base     < N_NODES) g_offp[base]     = excl;           excl += v0;
    if (base + 1 < N_NODES) g_offp[base + 1] = excl;           excl += v1;
    if (base + 2 < N_NODES) g_offp[base + 2] = excl;           excl += v2;
    if (base + 3 < N_NODES) g_offp[base + 3] = excl;
    if (tid == 255) g_bsum[blockIdx.x] = s[255];
}

// ---------------- scan stage 2 ----------------
__global__ void k_scan2() {
    __shared__ int s[128];
    const int tid = threadIdx.x;
    int v = (tid < NB_SCAN) ? g_bsum[tid] : 0;
    s[tid] = v;
    __syncthreads();
    for (int d = 1; d < 128; d <<= 1) {
        int t = 0;
        if (tid >= d) t = s[tid - d];
        __syncthreads();
        if (tid >= d) s[tid] += t;
        __syncthreads();
    }
    g_bsumx[tid] = s[tid] - v;
}

// ---------------- scan stage 3 ----------------
__global__ void k_scan3() {
    int i = blockIdx.x * 256 + threadIdx.x;
    if (i < N_NODES) {
        int o = g_offp[i] + g_bsumx[i >> 10];
        g_off[i] = o;
        g_cur[i] = o;
    }
    if (i == 0) g_off[N_NODES] = TE;
}

// ---------------- persistent GEMM: g_Xh = fp16(xh @ (Whi + Wlo)) -------------
__global__ void __launch_bounds__(256, 1) k_gemm() {
    extern __shared__ __half sm[];
    __half* WHI = sm;                  // 128*264 = 33792 halves
    __half* WLO = sm + 33792;
    __half* XB0 = sm + 67584;          // 64*264 = 16896 halves
    __half* XB1 = sm + 84480;          // total 101376 halves = 202752 B

    const int tid = threadIdx.x, lane = tid & 31, wid = tid >> 5;

    {
        const uint4* src = (const uint4*)g_Whl;   // 8192 uint4
        for (int i = tid; i < 8192; i += 256) {
            int hs = i >> 12;
            int j  = i & 4095;
            int r  = j >> 5, q = j & 31;
            __half* dst = hs ? WLO : WHI;
            *(uint4*)&dst[r*KP + q*8] = src[i];
        }
    }

    const int mt = wid & 3;
    const int nh = wid >> 2;
    const int wr = mt * 16;
    const int arow = wr + (lane & 15);
    const int acolofs = (lane & 16) ? 8 : 0;
    const int brow = ((lane & 16) ? 8 : 0) + (lane & 7);
    const int bko  = (lane & 8) ? 8 : 0;

    {
        const __half* gs = &g_Xi[(size_t)blockIdx.x * 64 * 256];
        #pragma unroll
        for (int j = 0; j < 8; j++) {
            int idx = tid + j*256;
            int r = idx >> 5, c = idx & 31;
            uint32_t da = (uint32_t)__cvta_generic_to_shared(&XB0[r*KP + c*8]);
            asm volatile("cp.async.cg.shared.global [%0], [%1], 16;"
                         :: "r"(da), "l"(gs + r*256 + c*8));
        }
        asm volatile("cp.async.commit_group;");
    }
    __syncthreads();

    int tile = blockIdx.x;
    for (int it = 0; tile < NTILE; it++, tile += NSM) {
        const int ntile = tile + NSM;
        __half* cur = (it & 1) ? XB1 : XB0;
        __half* nxt = (it & 1) ? XB0 : XB1;

        if (ntile < NTILE) {
            const __half* gs = &g_Xi[(size_t)ntile * 64 * 256];
            #pragma unroll
            for (int j = 0; j < 8; j++) {
                int idx = tid + j*256;
                int r = idx >> 5, c = idx & 31;
                uint32_t da = (uint32_t)__cvta_generic_to_shared(&nxt[r*KP + c*8]);
                asm volatile("cp.async.cg.shared.global [%0], [%1], 16;"
                             :: "r"(da), "l"(gs + r*256 + c*8));
            }
            asm volatile("cp.async.commit_group;");
            asm volatile("cp.async.wait_group 1;");
        } else {
            asm volatile("cp.async.wait_group 0;");
        }
        __syncthreads();

        float d[8][4];
        #pragma unroll
        for (int l = 0; l < 8; l++)
            #pragma unroll
            for (int j = 0; j < 4; j++) d[l][j] = 0.f;

        #pragma unroll 1
        for (int ks = 0; ks < 16; ks++) {
            uint32_t ah0, ah1, ah2, ah3;
            {
                int acol = ks*16 + acolofs;
                uint32_t aa = (uint32_t)__cvta_generic_to_shared(&cur[arow*KP + acol]);
                LDSM4(ah0, ah1, ah2, ah3, aa);
            }
            uint32_t bh[4][4], bl[4][4];
            #pragma unroll
            for (int p = 0; p < 4; p++) {
                int nrow = nh*64 + p*16 + brow;
                int kofs = ks*16 + bko;
                uint32_t ha = (uint32_t)__cvta_generic_to_shared(&WHI[nrow*KP + kofs]);
                uint32_t la = (uint32_t)__cvta_generic_to_shared(&WLO[nrow*KP + kofs]);
                LDSM4(bh[p][0], bh[p][1], bh[p][2], bh[p][3], ha);
                LDSM4(bl[p][0], bl[p][1], bl[p][2], bl[p][3], la);
            }
            #pragma unroll
            for (int l = 0; l < 8; l++) {
                int p = l >> 1, o = (l & 1) * 2;
                MMA16816(d[l], ah0, ah1, ah2, ah3, bh[p][o], bh[p][o+1]);
                MMA16816(d[l], ah0, ah1, ah2, ah3, bl[p][o], bl[p][o+1]);
            }
        }

        const int row0 = tile * 64;
        const int er0 = row0 + wr + (lane >> 2);
        const int ec  = (lane & 3) * 2;
        #pragma unroll
        for (int l = 0; l < 8; l++) {
            int n = (nh*8 + l)*8 + ec;
            if (er0 < N_NODES) {
                __half2 hp = __floats2half2_rn(d[l][0], d[l][1]);
                *(unsigned*)&g_Xh[(size_t)er0*128 + n] = *(unsigned*)&hp;
            }
            if (er0 + 8 < N_NODES) {
                __half2 hp = __floats2half2_rn(d[l][2], d[l][3]);
                *(unsigned*)&g_Xh[(size_t)(er0+8)*128 + n] = *(unsigned*)&hp;
            }
        }
        __syncthreads();
    }
}

// ---------------- bucket: CSR slots, pre-scaled fp16 weights (8B records) -----
__global__ void k_bucket(const int* __restrict__ ei, const float* __restrict__ ev) {
    const int t = blockIdx.y;
    const int e = blockIdx.x * 256 + threadIdx.x;
    if (e >= EDGES) return;
    int   row = __ldg(&ei[(t*2 + 0)*EDGES + e]);
    int   col = __ldg(&ei[(t*2 + 1)*EDGES + e]);
    float val = __ldg(&ev[t*EDGES + e]);
    int pos = atomicAdd(&g_cur[row], 1);
    __half2 w = __floats2half2_rn(val * g_sc[t], val * g_sc[4 + t]);
    g_epk[pos] = ((unsigned long long)(*(unsigned*)&w) << 32) | (unsigned)col;
}

// ---------------- gather: half-warp per edge, fp16 output ---------------------
__global__ void __launch_bounds__(256) k_gather(int n0, int n1) {
    const int lane = threadIdx.x & 31;
    const int half = lane >> 4;
    const int sub  = lane & 15;
    const int n = n0 + blockIdx.x * 8 + (threadIdx.x >> 5);
    if (n >= n1) return;

    const int s0 = __ldg(&g_off[n]);
    const int s1 = __ldg(&g_off[n + 1]);

    float acc[8];
    #pragma unroll
    for (int i = 0; i < 8; i++) acc[i] = 0.f;
    const bool ch1 = (sub >= 8);

    for (int e2 = s0; e2 < s1; e2 += 8) {
        const int eA = e2 + half;
        const int eB = eA + 2;
        const int eC = eA + 4;
        const int eD = eA + 6;
        unsigned long long pA = (eA < s1) ? __ldg(&g_epk[eA]) : 0ull;
        unsigned long long pB = (eB < s1) ? __ldg(&g_epk[eB]) : 0ull;
        unsigned long long pC = (eC < s1) ? __ldg(&g_epk[eC]) : 0ull;
        unsigned long long pD = (eD < s1) ? __ldg(&g_epk[eD]) : 0ull;
        unsigned cA = (unsigned)pA & 0x1FFFFu;
        unsigned cB = (unsigned)pB & 0x1FFFFu;
        unsigned cC = (unsigned)pC & 0x1FFFFu;
        unsigned cD = (unsigned)pD & 0x1FFFFu;
        uint4 vA = __ldg((const uint4*)&g_Xh[(size_t)cA*128 + sub*8]);
        uint4 vB = __ldg((const uint4*)&g_Xh[(size_t)cB*128 + sub*8]);
        uint4 vC = __ldg((const uint4*)&g_Xh[(size_t)cC*128 + sub*8]);
        uint4 vD = __ldg((const uint4*)&g_Xh[(size_t)cD*128 + sub*8]);
        unsigned wAb = (unsigned)(pA >> 32);
        unsigned wBb = (unsigned)(pB >> 32);
        unsigned wCb = (unsigned)(pC >> 32);
        unsigned wDb = (unsigned)(pD >> 32);
        __half2 wA2 = *(__half2*)&wAb;
        __half2 wB2 = *(__half2*)&wBb;
        __half2 wC2 = *(__half2*)&wCb;
        __half2 wD2 = *(__half2*)&wDb;
        float wA = ch1 ? __high2float(wA2) : __low2float(wA2);
        float wB = ch1 ? __high2float(wB2) : __low2float(wB2);
        float wC = ch1 ? __high2float(wC2) : __low2float(wC2);
        float wD = ch1 ? __high2float(wD2) : __low2float(wD2);

        {
            float2 a0 = __half22float2(*(__half2*)&vA.x);
            float2 a1 = __half22float2(*(__half2*)&vA.y);
            float2 a2 = __half22float2(*(__half2*)&vA.z);
            float2 a3 = __half22float2(*(__half2*)&vA.w);
            acc[0] = fmaf(a0.x, wA, acc[0]); acc[1] = fmaf(a0.y, wA, acc[1]);
            acc[2] = fmaf(a1.x, wA, acc[2]); acc[3] = fmaf(a1.y, wA, acc[3]);
            acc[4] = fmaf(a2.x, wA, acc[4]); acc[5] = fmaf(a2.y, wA, acc[5]);
            acc[6] = fmaf(a3.x, wA, acc[6]); acc[7] = fmaf(a3.y, wA, acc[7]);
        }
        {
            float2 b0 = __half22float2(*(__half2*)&vB.x);
            float2 b1 = __half22float2(*(__half2*)&vB.y);
            float2 b2 = __half22float2(*(__half2*)&vB.z);
            float2 b3 = __half22float2(*(__half2*)&vB.w);
            acc[0] = fmaf(b0.x, wB, acc[0]); acc[1] = fmaf(b0.y, wB, acc[1]);
            acc[2] = fmaf(b1.x, wB, acc[2]); acc[3] = fmaf(b1.y, wB, acc[3]);
            acc[4] = fmaf(b2.x, wB, acc[4]); acc[5] = fmaf(b2.y, wB, acc[5]);
            acc[6] = fmaf(b3.x, wB, acc[6]); acc[7] = fmaf(b3.y, wB, acc[7]);
        }
        {
            float2 c0 = __half22float2(*(__half2*)&vC.x);
            float2 c1 = __half22float2(*(__half2*)&vC.y);
            float2 c2 = __half22float2(*(__half2*)&vC.z);
            float2 c3 = __half22float2(*(__half2*)&vC.w);
            acc[0] = fmaf(c0.x, wC, acc[0]); acc[1] = fmaf(c0.y, wC, acc[1]);
            acc[2] = fmaf(c1.x, wC, acc[2]); acc[3] = fmaf(c1.y, wC, acc[3]);
            acc[4] = fmaf(c2.x, wC, acc[4]); acc[5] = fmaf(c2.y, wC, acc[5]);
            acc[6] = fmaf(c3.x, wC, acc[6]); acc[7] = fmaf(c3.y, wC, acc[7]);
        }
        {
            float2 d0 = __half22float2(*(__half2*)&vD.x);
            float2 d1 = __half22float2(*(__half2*)&vD.y);
            float2 d2 = __half22float2(*(__half2*)&vD.z);
            float2 d3 = __half22float2(*(__half2*)&vD.w);
            acc[0] = fmaf(d0.x, wD, acc[0]); acc[1] = fmaf(d0.y, wD, acc[1]);
            acc[2] = fmaf(d1.x, wD, acc[2]); acc[3] = fmaf(d1.y, wD, acc[3]);
            acc[4] = fmaf(d2.x, wD, acc[4]); acc[5] = fmaf(d2.y, wD, acc[5]);
            acc[6] = fmaf(d3.x, wD, acc[6]); acc[7] = fmaf(d3.y, wD, acc[7]);
        }
    }

    #pragma unroll
    for (int i = 0; i < 8; i++)
        acc[i] += __shfl_xor_sync(0xffffffffu, acc[i], 16);

    if (half == 0) {
        uint4 xv = __ldg((const uint4*)&g_Xh[(size_t)n*128 + sub*8]);
        float2 x0 = __half22float2(*(__half2*)&xv.x);
        float2 x1 = __half22float2(*(__half2*)&xv.y);
        float2 x2 = __half22float2(*(__half2*)&xv.z);
        float2 x3 = __half22float2(*(__half2*)&xv.w);
        __half2 h0 = __floats2half2_rn(fmaxf(fmaf(BETA, x0.x, acc[0]), 0.f),
                                       fmaxf(fmaf(BETA, x0.y, acc[1]), 0.f));
        __half2 h1 = __floats2half2_rn(fmaxf(fmaf(BETA, x1.x, acc[2]), 0.f),
                                       fmaxf(fmaf(BETA, x1.y, acc[3]), 0.f));
        __half2 h2 = __floats2half2_rn(fmaxf(fmaf(BETA, x2.x, acc[4]), 0.f),
                                       fmaxf(fmaf(BETA, x2.y, acc[5]), 0.f));
        __half2 h3 = __floats2half2_rn(fmaxf(fmaf(BETA, x3.x, acc[6]), 0.f),
                                       fmaxf(fmaf(BETA, x3.y, acc[7]), 0.f));
        uint4 o;
        o.x = *(unsigned*)&h0; o.y = *(unsigned*)&h1;
        o.z = *(unsigned*)&h2; o.w = *(unsigned*)&h3;
        *(uint4*)&g_AccH[(size_t)n*128 + sub*8] = o;
    }
}

// ---------------- lin1 via mma.sync: H2 = relu(AccH @ (W1hi+W1lo)^T + b1) ----
// 64 rows/CTA, 8 warps: mt = wid&3 (16 rows), nh = wid>>2 (32 cols).
__global__ void __launch_bounds__(256) k_lin1h(const float* __restrict__ b1,
                                               int row_base) {
    extern __shared__ __half smh[];
    __half* W1HI = smh;                    // 64*136
    __half* W1LO = smh + 64*KP2;
    __half* At   = smh + 2*64*KP2;         // 64*136; total 26112 halves = 52224 B

    const int tid = threadIdx.x, lane = tid & 31, wid = tid >> 5;

    // copy W1 hi/lo (2048 uint4) with KP2 padding
    {
        const uint4* src = (const uint4*)g_W1hl;
        for (int i = tid; i < 2048; i += 256) {
            int hs = i >> 10;
            int j  = i & 1023;
            int r  = j >> 4, q = j & 15;
            __half* dst = hs ? W1LO : W1HI;
            *(uint4*)&dst[r*KP2 + q*8] = src[i];
        }
    }

    // load A tile: 64 rows x 128 halves (1024 uint4)
    const int row0 = row_base + blockIdx.x * 64;
    for (int i = tid; i < 1024; i += 256) {
        int r = i >> 4, q = i & 15;
        int row = row0 + r;
        uint4 v = make_uint4(0u, 0u, 0u, 0u);
        if (row < N_NODES) v = *(const uint4*)&g_AccH[(size_t)row*128 + q*8];
        *(uint4*)&At[r*KP2 + q*8] = v;
    }
    __syncthreads();

    float d[4][4];
    #pragma unroll
    for (int l = 0; l < 4; l++)
        #pragma unroll
        for (int j = 0; j < 4; j++) d[l][j] = 0.f;

    const int mt = wid & 3;
    const int nh = wid >> 2;
    const int wr = mt * 16;
    const int arow = wr + (lane & 15);
    const int acolofs = (lane & 16) ? 8 : 0;
    const int brow = ((lane & 16) ? 8 : 0) + (lane & 7);
    const int bko  = (lane & 8) ? 8 : 0;

    #pragma unroll
    for (int ks = 0; ks < 8; ks++) {
        uint32_t ah0, ah1, ah2, ah3;
        {
            int acol = ks*16 + acolofs;
            uint32_t aa = (uint32_t)__cvta_generic_to_shared(&At[arow*KP2 + acol]);
            LDSM4(ah0, ah1, ah2, ah3, aa);
        }
        uint32_t bh[2][4], bl[2][4];
        #pragma unroll
        for (int p = 0; p < 2; p++) {
            int nrow = nh*32 + p*16 + brow;
            int kofs = ks*16 + bko;
            uint32_t ha = (uint32_t)__cvta_generic_to_shared(&W1HI[nrow*KP2 + kofs]);
            uint32_t la = (uint32_t)__cvta_generic_to_shared(&W1LO[nrow*KP2 + kofs]);
            LDSM4(bh[p][0], bh[p][1], bh[p][2], bh[p][3], ha);
            LDSM4(bl[p][0], bl[p][1], bl[p][2], bl[p][3], la);
        }
        #pragma unroll
        for (int l = 0; l < 4; l++) {
            int p = l >> 1, o = (l & 1) * 2;
            MMA16816(d[l], ah0, ah1, ah2, ah3, bh[p][o], bh[p][o+1]);
            MMA16816(d[l], ah0, ah1, ah2, ah3, bl[p][o], bl[p][o+1]);
        }
    }

    // epilogue: bias + relu, fp32 store
    const int er0 = row0 + wr + (lane >> 2);
    const int ec  = (lane & 3) * 2;
    #pragma unroll
    for (int l = 0; l < 4; l++) {
        int n = nh*32 + l*8 + ec;
        float2 bb = *(const float2*)&b1[n];
        if (er0 < N_NODES) {
            float2 o = make_float2(fmaxf(d[l][0] + bb.x, 0.f),
                                   fmaxf(d[l][1] + bb.y, 0.f));
            *(float2*)&g_H2[(size_t)er0*64 + n] = o;
        }
        if (er0 + 8 < N_NODES) {
            float2 o = make_float2(fmaxf(d[l][2] + bb.x, 0.f),
                                   fmaxf(d[l][3] + bb.y, 0.f));
            *(float2*)&g_H2[(size_t)(er0+8)*64 + n] = o;
        }
    }
}

// ---------------- head: y + loss terms ----------------
__global__ void k_head(const float* __restrict__ lw, const float* __restrict__ lb,
                       const int* __restrict__ tx, const int* __restrict__ tg,
                       float* __restrict__ yout) {
    __shared__ float Wls[4*64 + 4];
    __shared__ float red[256];
    const int tid = threadIdx.x;
    for (int i = tid; i < 260; i += 256) Wls[i] = (i < 256) ? lw[i] : lb[i - 256];
    __syncthreads();

    const int i = blockIdx.x * 256 + tid;
    float lsum = 0.f;
    if (i < MTGT) {
        const int node = __ldg(&tx[i]);
        float l0 = Wls[256], l1 = Wls[257], l2 = Wls[258], l3 = Wls[259];
        const float* h = &g_H2[(size_t)node*64];
        #pragma unroll
        for (int k = 0; k < 64; k += 4) {
            float4 hv = *(const float4*)&h[k];
            l0 += hv.x*Wls[0*64+k] + hv.y*Wls[0*64+k+1] + hv.z*Wls[0*64+k+2] + hv.w*Wls[0*64+k+3];
            l1 += hv.x*Wls[1*64+k] + hv.y*Wls[1*64+k+1] + hv.z*Wls[1*64+k+2] + hv.w*Wls[1*64+k+3];
            l2 += hv.x*Wls[2*64+k] + hv.y*Wls[2*64+k+1] + hv.z*Wls[2*64+k+2] + hv.w*Wls[2*64+k+3];
            l3 += hv.x*Wls[3*64+k] + hv.y*Wls[3*64+k+1] + hv.z*Wls[3*64+k+2] + hv.w*Wls[3*64+k+3];
        }
        yout[i*4+0] = l0; yout[i*4+1] = l1; yout[i*4+2] = l2; yout[i*4+3] = l3;
        float m  = fmaxf(fmaxf(l0, l1), fmaxf(l2, l3));
        float se = expf(l0-m) + expf(l1-m) + expf(l2-m) + expf(l3-m);
        float lse = m + logf(se);
        int t = __ldg(&tg[i]);
        float lt = (t == 0) ? l0 : (t == 1) ? l1 : (t == 2) ? l2 : l3;
        lsum = lse - lt;
    }
    red[tid] = lsum;
    __syncthreads();
    #pragma unroll
    for (int s = 128; s > 0; s >>= 1) {
        if (tid < s) red[tid] += red[tid + s];
        __syncthreads();
    }
    if (tid == 0) atomicAdd(&g_loss, red[0]);
}

__global__ void k_fin(float* __restrict__ out, int write_loss) {
    if (write_loss) out[0] = g_loss / (float)MTGT;
}

// ---------------- launch ----------------
extern "C" void kernel_launch(void* const* d_in, const int* in_sizes, int n_in,
                              void* d_out, int out_size) {
    const float* X  = (const float*)d_in[0];
    const float* ev = (const float*)d_in[1];
    const float* Ws = (const float*)d_in[2];
    const float* cw = (const float*)d_in[3];
    const float* W1 = (const float*)d_in[4];
    const float* b1 = (const float*)d_in[5];
    const float* lw = (const float*)d_in[6];
    const float* lb = (const float*)d_in[7];
    const int*   ei = (const int*)d_in[8];
    const int*   tx = (const int*)d_in[9];
    const int*   tg = (const int*)d_in[10];
    float* out = (float*)d_out;

    float* yscratch = nullptr;
    cudaGetSymbolAddress((void**)&yscratch, g_y);

    float* yout;
    int write_loss;
    if (out_size == MTGT*4 + 1)      { yout = out + 1;  write_loss = 1; }
    else if (out_size == MTGT*4)     { yout = out;      write_loss = 0; }
    else                             { yout = yscratch; write_loss = 1; }

    static cudaStream_t s2 = nullptr;
    static cudaEvent_t ev_fork = nullptr, ev_join = nullptr, ev_gA = nullptr, ev_l1 = nullptr;
    if (s2 == nullptr) {
        cudaStreamCreateWithFlags(&s2, cudaStreamNonBlocking);
        cudaEventCreateWithFlags(&ev_fork, cudaEventDisableTiming);
        cudaEventCreateWithFlags(&ev_join, cudaEventDisableTiming);
        cudaEventCreateWithFlags(&ev_gA, cudaEventDisableTiming);
        cudaEventCreateWithFlags(&ev_l1, cudaEventDisableTiming);
    }

    cudaEventRecord(ev_fork, 0);
    cudaStreamWaitEvent(s2, ev_fork, 0);

    // ---- default stream: X convert + W/W1 prep ----
    k_prepX<<<(NTILE*64*64 + 255)/256, 256>>>(X, Ws, W1);

    // ---- branch B (s2): zero + scales ----
    dim3 eg((EDGES + 255)/256, TTYPE);
    k_zero<<<(N_NODES + 255)/256, 256, 0, s2>>>(cw);

    // ---- branch A (default): persistent GEMM ----
    const int gemm_smem = 101376 * sizeof(__half);   // 202752 B
    cudaFuncSetAttribute(k_gemm, cudaFuncAttributeMaxDynamicSharedMemorySize, gemm_smem);
    k_gemm<<<NSM, 256, gemm_smem>>>();

    // ---- branch B (s2): hist + scan + bucket ----
    k_hist<<<eg, 256, 0, s2>>>(ei);
    k_scan1<<<NB_SCAN, 256, 0, s2>>>();
    k_scan2<<<1, 128, 0, s2>>>();
    k_scan3<<<(N_NODES + 255)/256, 256, 0, s2>>>();
    k_bucket<<<eg, 256, 0, s2>>>(ei, ev);
    cudaEventRecord(ev_join, s2);

    // ---- join ----
    cudaStreamWaitEvent(0, ev_join, 0);

    const int lin1_smem = 26112 * sizeof(__half);    // 52224 B
    cudaFuncSetAttribute(k_lin1h, cudaFuncAttributeMaxDynamicSharedMemorySize, lin1_smem);

    // ---- pipelined gather/lin1 ----
    k_gather<<<NSPLIT/8, 256>>>(0, NSPLIT);                       // gather A
    cudaEventRecord(ev_gA, 0);
    cudaStreamWaitEvent(s2, ev_gA, 0);
    k_lin1h<<<NSPLIT/64, 256, lin1_smem, s2>>>(b1, 0);            // lin1 A ∥ gather B
    cudaEventRecord(ev_l1, s2);
    k_gather<<<(N_NODES - NSPLIT + 7)/8, 256>>>(NSPLIT, N_NODES); // gather B
    k_lin1h<<<(N_NODES - NSPLIT + 63)/64, 256, lin1_smem>>>(b1, NSPLIT); // lin1 B
    cudaStreamWaitEvent(0, ev_l1, 0);

    k_head<<<(MTGT + 255)/256, 256>>>(lw, lb, tx, tg, yout);
    k_fin<<<1, 1>>>(out, write_loss);
}